// round 5
// baseline (speedup 1.0000x reference)
#include <cuda_runtime.h>
#include <cstdint>

// Problem constants
#define NUM_VERTS 6890
#define NUM_FACES 13776
#define HW (1024 * 1024)
#define NBATCH 16
#define THREADS 256
#define PX_PER_THREAD 4
#define PX_PER_TILE (THREADS * PX_PER_THREAD)       // 1024 pixels
#define TILE_FLOATS (PX_PER_TILE * 3)               // 3072 floats
#define TILE_BYTES (TILE_FLOATS * 4)                // 12288 B
#define TILES_PER_BLOCK 4
#define NUM_BLOCKS (HW / (PX_PER_TILE * TILES_PER_BLOCK))   // 256

// Exploits:
//  1. Reference gathers only batch-0 faces/verts, broadcasts (H,W,3) over 16
//     batches -> compute once, TMA-replicate 16x from smem.
//  2. JAX x64 disabled -> index tensors are int32 on device.
//  3. R4 lesson: keep the two-level gather (82KB verts + 165KB faces stay
//     L1-hot); the packed-table variant pushed gathers to L2 and regressed.
//  4. R5: double-buffered multi-tile pipeline so TMA store of tile t overlaps
//     gather/compute of tile t+1 (R3/R4 ncu: issue<4%, block life was
//     gather-chain + full TMA drain back-to-back).

__global__ __launch_bounds__(THREADS) void uv_render_kernel(
    const float* __restrict__ verts,   // (16, 6890, 3) fp32 — batch 0 only
    const int*   __restrict__ faces,   // (13776, 3) int32
    const int*   __restrict__ pix,     // (1024, 1024) int32
    const float* __restrict__ bary,    // (1024, 1024, 3) fp32
    float* __restrict__ out)           // (16, 1024, 1024, 3) fp32
{
    __shared__ __align__(128) float tile[2][TILE_FLOATS];   // 2 x 12 KB

    uint32_t sbase;
    asm("{ .reg .u64 tmp; cvta.to.shared.u64 tmp, %1; cvt.u32.u64 %0, tmp; }"
        : "=r"(sbase) : "l"(&tile[0][0]));

    const size_t bstride = (size_t)HW * 3;

#pragma unroll
    for (int tl = 0; tl < TILES_PER_BLOCK; tl++) {
        const int tile_id = blockIdx.x * TILES_PER_BLOCK + tl;
        const int p0 = tile_id * PX_PER_TILE + threadIdx.x * PX_PER_THREAD;
        const int buf = tl & 1;

        // ---- 4 pixel ids ----
        const int4 pi = *reinterpret_cast<const int4*>(pix + p0);
        int pf[4] = { pi.x, pi.y, pi.z, pi.w };

        // ---- 12 bary coords ----
        const float4* b4 = reinterpret_cast<const float4*>(bary + (size_t)p0 * 3);
        float4 bA = b4[0], bB = b4[1], bC = b4[2];
        const float bar[12] = { bA.x, bA.y, bA.z, bA.w,
                                bB.x, bB.y, bB.z, bB.w,
                                bC.x, bC.y, bC.z, bC.w };

        // ---- phase 1: 12 face-vertex indices in flight ----
        int vid[4][3];
#pragma unroll
        for (int i = 0; i < 4; i++) {
            int f = pf[i];
            f = (f < 0 || f >= NUM_FACES) ? 0 : f;
            const int* fr = faces + f * 3;
#pragma unroll
            for (int k = 0; k < 3; k++) vid[i][k] = fr[k];
        }

        // ---- phase 2: 36 vertex components in flight (L1-hot 82KB table) ----
        float va[4][3][3];
#pragma unroll
        for (int i = 0; i < 4; i++) {
#pragma unroll
            for (int k = 0; k < 3; k++) {
                int vi = vid[i][k];
                vi = (vi < 0 || vi >= NUM_VERTS) ? 0 : vi;
                const float* vp = verts + vi * 3;
                va[i][k][0] = vp[0];
                va[i][k][1] = vp[1];
                va[i][k][2] = vp[2];
            }
        }

        // ---- phase 3: weighted sum + bg mask ----
        float res[12];
#pragma unroll
        for (int i = 0; i < 4; i++) {
            const float m = (pf[i] >= 0) ? 1.0f : 0.0f;
#pragma unroll
            for (int d = 0; d < 3; d++) {
                res[i * 3 + d] = (bar[i * 3 + 0] * va[i][0][d]
                                + bar[i * 3 + 1] * va[i][1][d]
                                + bar[i * 3 + 2] * va[i][2][d]) * m;
            }
        }

        // Buffer reuse safety: after thread0's wait_group.read 1 (end of
        // iteration tl-1), at most group tl-1 is outstanding, so group tl-2
        // (this buffer) has been fully read. Barrier publishes that to all.
        __syncthreads();

        // ---- tile to smem ----
        {
            float4* t4 = reinterpret_cast<float4*>(&tile[buf][0]) + threadIdx.x * 3;
            t4[0] = make_float4(res[0], res[1], res[2],  res[3]);
            t4[1] = make_float4(res[4], res[5], res[6],  res[7]);
            t4[2] = make_float4(res[8], res[9], res[10], res[11]);
        }
        __syncthreads();

        // ---- thread0: issue 16 bulk stores, keep <=1 group outstanding ----
        if (threadIdx.x == 0) {
            asm volatile("fence.proxy.async.shared::cta;" ::: "memory");
            const uint32_t saddr = sbase + buf * TILE_BYTES;
            const size_t gbase = (size_t)tile_id * TILE_FLOATS;
#pragma unroll
            for (int n = 0; n < NBATCH; n++) {
                float* dst = out + gbase + (size_t)n * bstride;
                asm volatile(
                    "cp.async.bulk.global.shared::cta.bulk_group [%0], [%1], %2;"
                    :: "l"(dst), "r"(saddr), "n"(TILE_BYTES) : "memory");
            }
            asm volatile("cp.async.bulk.commit_group;" ::: "memory");
            asm volatile("cp.async.bulk.wait_group.read 1;" ::: "memory");
        }
    }

    // final drain
    if (threadIdx.x == 0) {
        asm volatile("cp.async.bulk.wait_group 0;" ::: "memory");
    }
}

extern "C" void kernel_launch(void* const* d_in, const int* in_sizes, int n_in,
                              void* d_out, int out_size)
{
    const float* verts = (const float*)d_in[0];
    const int*   faces = (const int*)d_in[1];
    const int*   pix   = (const int*)d_in[2];
    const float* bary  = (const float*)d_in[3];
    float* out = (float*)d_out;

    uv_render_kernel<<<NUM_BLOCKS, THREADS>>>(verts, faces, pix, bary, out);
}

// round 10
// speedup vs baseline: 1.1140x; 1.1140x over previous
#include <cuda_runtime.h>
#include <cstdint>

// Problem constants
#define NUM_VERTS 6890
#define NUM_FACES 13776
#define HW (1024 * 1024)
#define NBATCH 16
#define THREADS 256
#define PX_PER_THREAD 4
#define PX_PER_TILE (THREADS * PX_PER_THREAD)   // 1024
#define TILE_FLOATS (PX_PER_TILE * 3)           // 3072
#define TILE_BYTES (TILE_FLOATS * 4)            // 12288
#define VERT_FLOATS (NUM_VERTS * 3)             // 20670
#define VERT_F4 ((VERT_FLOATS + 3) / 4)         // 5168 float4 (reads 2 pad floats, in-bounds)
#define SMEM_FLOATS (TILE_FLOATS + VERT_F4 * 4) // 23744 floats
#define SMEM_BYTES (SMEM_FLOATS * 4)            // 94976 B -> 2 blocks/SM

// Exploits / lessons:
//  1. Reference uses only batch-0 faces/verts, broadcasts (H,W,3) over 16
//     batches -> compute once, TMA-replicate 16x from smem.
//  2. Index tensors are int32 on device (JAX x64 off).
//  3. R3 ncu: L1tex wavefronts from 36 scattered LDG.32 vert gathers/thread
//     (~1150 wf-cyc/warp) are the binding cost. Fix: verts table in SMEM
//     (LDS ~4 cyc vs ~32 wf), faces packed to ushort4 (3 LDG.32 -> 1 LDG.64).
//  4. R5 lesson: keep grid=1024; block-level pipelining killed parallelism.

__device__ __align__(8) ushort4 g_pface[NUM_FACES];

__global__ __launch_bounds__(256) void prep_faces_kernel(const int* __restrict__ faces)
{
    const int f = blockIdx.x * blockDim.x + threadIdx.x;
    if (f >= NUM_FACES) return;
    int v0 = faces[f * 3 + 0];
    int v1 = faces[f * 3 + 1];
    int v2 = faces[f * 3 + 2];
    v0 = (v0 < 0 || v0 >= NUM_VERTS) ? 0 : v0;
    v1 = (v1 < 0 || v1 >= NUM_VERTS) ? 0 : v1;
    v2 = (v2 < 0 || v2 >= NUM_VERTS) ? 0 : v2;
    g_pface[f] = make_ushort4((unsigned short)v0, (unsigned short)v1,
                              (unsigned short)v2, 0);
}

__global__ __launch_bounds__(THREADS) void uv_render_kernel(
    const float* __restrict__ verts,   // (16, 6890, 3) fp32 — batch 0 only
    const int*   __restrict__ pix,     // (1024, 1024) int32
    const float* __restrict__ bary,    // (1024, 1024, 3) fp32
    float* __restrict__ out)           // (16, 1024, 1024, 3) fp32
{
    extern __shared__ __align__(128) float smem[];
    float* tile   = smem;                       // 3072 floats (TMA source)
    float* sverts = smem + TILE_FLOATS;         // 20672 floats (vertex table)

    const int t  = blockIdx.x * blockDim.x + threadIdx.x;
    const int p0 = t * PX_PER_THREAD;

    // ---- streaming inputs (evict-first; keep L1 for the packed face table) ----
    const int4 pi = __ldcs(reinterpret_cast<const int4*>(pix + p0));
    int pf[4] = { pi.x, pi.y, pi.z, pi.w };

    const float4* b4 = reinterpret_cast<const float4*>(bary + (size_t)p0 * 3);
    float4 bA = __ldcs(b4 + 0), bB = __ldcs(b4 + 1), bC = __ldcs(b4 + 2);
    const float bar[12] = { bA.x, bA.y, bA.z, bA.w,
                            bB.x, bB.y, bB.z, bB.w,
                            bC.x, bC.y, bC.z, bC.w };

    // ---- packed face records: 4 independent LDG.64 into 110KB L1-hot table ----
    ushort4 q[4];
#pragma unroll
    for (int i = 0; i < 4; i++) {
        int f = pf[i];
        f = (f < 0 || f >= NUM_FACES) ? 0 : f;   // bg -> face 0, masked later
        q[i] = g_pface[f];
    }

    // ---- fill vertex table into smem (vectorized, L2-broadcast-hot) ----
    {
        const float4* v4 = reinterpret_cast<const float4*>(verts);
        float4* s4 = reinterpret_cast<float4*>(sverts);
        for (int i = threadIdx.x; i < VERT_F4; i += THREADS)
            s4[i] = v4[i];
    }
    __syncthreads();

    // ---- vertex gathers via LDS (random banking ~4 cyc vs ~32 L1 wavefronts) ----
    float res[12];
#pragma unroll
    for (int i = 0; i < 4; i++) {
        const int i0 = q[i].x * 3, i1 = q[i].y * 3, i2 = q[i].z * 3;
        const float m = (pf[i] >= 0) ? 1.0f : 0.0f;
        const float b0 = bar[i * 3 + 0], b1 = bar[i * 3 + 1], b2 = bar[i * 3 + 2];
#pragma unroll
        for (int d = 0; d < 3; d++) {
            res[i * 3 + d] = (b0 * sverts[i0 + d]
                            + b1 * sverts[i1 + d]
                            + b2 * sverts[i2 + d]) * m;
        }
    }

    // ---- result tile to smem ----
    {
        float4* t4 = reinterpret_cast<float4*>(tile) + threadIdx.x * 3;
        t4[0] = make_float4(res[0], res[1], res[2],  res[3]);
        t4[1] = make_float4(res[4], res[5], res[6],  res[7]);
        t4[2] = make_float4(res[8], res[9], res[10], res[11]);
    }
    __syncthreads();

    // ---- thread0: TMA bulk-store tile to all 16 batch slices ----
    if (threadIdx.x == 0) {
        asm volatile("fence.proxy.async.shared::cta;" ::: "memory");
        uint32_t saddr;
        asm("{ .reg .u64 tmp; cvta.to.shared.u64 tmp, %1; cvt.u32.u64 %0, tmp; }"
            : "=r"(saddr) : "l"(tile));
        const size_t gbase   = (size_t)blockIdx.x * TILE_FLOATS;
        const size_t bstride = (size_t)HW * 3;
#pragma unroll
        for (int n = 0; n < NBATCH; n++) {
            float* dst = out + gbase + (size_t)n * bstride;
            asm volatile(
                "cp.async.bulk.global.shared::cta.bulk_group [%0], [%1], %2;"
                :: "l"(dst), "r"(saddr), "n"(TILE_BYTES) : "memory");
        }
        asm volatile("cp.async.bulk.commit_group;" ::: "memory");
        asm volatile("cp.async.bulk.wait_group 0;" ::: "memory");
    }
}

extern "C" void kernel_launch(void* const* d_in, const int* in_sizes, int n_in,
                              void* d_out, int out_size)
{
    const float* verts = (const float*)d_in[0];
    const int*   faces = (const int*)d_in[1];
    const int*   pix   = (const int*)d_in[2];
    const float* bary  = (const float*)d_in[3];
    float* out = (float*)d_out;

    cudaFuncSetAttribute(uv_render_kernel,
                         cudaFuncAttributeMaxDynamicSharedMemorySize, SMEM_BYTES);

    prep_faces_kernel<<<(NUM_FACES + 255) / 256, 256>>>(faces);
    uv_render_kernel<<<HW / PX_PER_TILE, THREADS, SMEM_BYTES>>>(verts, pix, bary, out);
}

// round 11
// speedup vs baseline: 1.1534x; 1.0354x over previous
#include <cuda_runtime.h>
#include <cstdint>

// Problem constants
#define NUM_VERTS 6890
#define NUM_FACES 13776
#define HW (1024 * 1024)
#define NBATCH 16
#define THREADS 256
#define PX_PER_THREAD 4
#define PX_PER_TILE (THREADS * PX_PER_THREAD)   // 1024
#define TILE_FLOATS (PX_PER_TILE * 3)           // 3072
#define TILE_BYTES (TILE_FLOATS * 4)            // 12288

// Exploits / lessons:
//  1. Reference uses only batch-0 faces/verts and broadcasts (H,W,3) over all
//     16 batches -> compute once, TMA-replicate 16x from smem (R3 structure).
//  2. Index tensors are int32 on device (JAX x64 off).
//  3. R3 ncu: binding cost = L1tex wavefronts of scattered LDG.32 gathers.
//     R4 lesson: packed tables must FIT L1 (661KB fattr pack regressed).
//     R10 lesson: no big smem tables (redundant fill + occupancy collapse).
//     Fix: float4-padded verts (110KB) + ushort4 faces (110KB) = 220KB, both
//     L1-resident; gathers become 1 LDG.64 + 3 LDG.128 per pixel (3x fewer
//     wavefronts), streams use __ldcs to not evict the tables.

__device__ __align__(16) float4  g_pvert[NUM_VERTS];   // (x,y,z,0) per vertex
__device__ __align__(8)  ushort4 g_pface[NUM_FACES];   // 3 vertex ids, packed

__global__ __launch_bounds__(256) void prep_kernel(
    const float* __restrict__ verts,   // (16, 6890, 3) — batch 0 only
    const int*   __restrict__ faces)   // (13776, 3) int32
{
    const int i = blockIdx.x * blockDim.x + threadIdx.x;
    if (i < NUM_FACES) {
        int v0 = faces[i * 3 + 0];
        int v1 = faces[i * 3 + 1];
        int v2 = faces[i * 3 + 2];
        v0 = (v0 < 0 || v0 >= NUM_VERTS) ? 0 : v0;
        v1 = (v1 < 0 || v1 >= NUM_VERTS) ? 0 : v1;
        v2 = (v2 < 0 || v2 >= NUM_VERTS) ? 0 : v2;
        g_pface[i] = make_ushort4((unsigned short)v0, (unsigned short)v1,
                                  (unsigned short)v2, 0);
    }
    if (i < NUM_VERTS) {
        const float* vp = verts + i * 3;
        g_pvert[i] = make_float4(vp[0], vp[1], vp[2], 0.0f);
    }
}

__global__ __launch_bounds__(THREADS, 4) void uv_render_kernel(
    const int*   __restrict__ pix,     // (1024, 1024) int32
    const float* __restrict__ bary,    // (1024, 1024, 3) fp32
    float* __restrict__ out)           // (16, 1024, 1024, 3) fp32
{
    __shared__ __align__(128) float tile[TILE_FLOATS];   // 12 KB TMA source

    const int t  = blockIdx.x * blockDim.x + threadIdx.x;
    const int p0 = t * PX_PER_THREAD;

    // ---- streaming inputs, evict-first (preserve L1 for the two tables) ----
    const int4 pi = __ldcs(reinterpret_cast<const int4*>(pix + p0));
    int pf[4] = { pi.x, pi.y, pi.z, pi.w };

    const float4* b4 = reinterpret_cast<const float4*>(bary + (size_t)p0 * 3);
    float4 bA = __ldcs(b4 + 0), bB = __ldcs(b4 + 1), bC = __ldcs(b4 + 2);
    const float bar[12] = { bA.x, bA.y, bA.z, bA.w,
                            bB.x, bB.y, bB.z, bB.w,
                            bC.x, bC.y, bC.z, bC.w };

    // ---- 4 face records: independent LDG.64 into 110KB L1-hot table ----
    ushort4 q[4];
#pragma unroll
    for (int i = 0; i < 4; i++) {
        int f = pf[i];
        f = (f < 0 || f >= NUM_FACES) ? 0 : f;   // bg -> face 0, masked later
        q[i] = g_pface[f];
    }

    // ---- 12 vertex records: independent LDG.128 into 110KB L1-hot table ----
    float res[12];
#pragma unroll
    for (int i = 0; i < 4; i++) {
        float4 v0 = g_pvert[q[i].x];
        float4 v1 = g_pvert[q[i].y];
        float4 v2 = g_pvert[q[i].z];
        const float m  = (pf[i] >= 0) ? 1.0f : 0.0f;
        const float b0 = bar[i * 3 + 0], b1 = bar[i * 3 + 1], b2 = bar[i * 3 + 2];
        res[i * 3 + 0] = (b0 * v0.x + b1 * v1.x + b2 * v2.x) * m;
        res[i * 3 + 1] = (b0 * v0.y + b1 * v1.y + b2 * v2.y) * m;
        res[i * 3 + 2] = (b0 * v0.z + b1 * v1.z + b2 * v2.z) * m;
    }

    // ---- result tile to smem (3x STS.128) ----
    {
        float4* t4 = reinterpret_cast<float4*>(tile) + threadIdx.x * 3;
        t4[0] = make_float4(res[0], res[1], res[2],  res[3]);
        t4[1] = make_float4(res[4], res[5], res[6],  res[7]);
        t4[2] = make_float4(res[8], res[9], res[10], res[11]);
    }
    __syncthreads();

    // ---- thread0: TMA bulk-store tile to all 16 batch slices ----
    if (threadIdx.x == 0) {
        asm volatile("fence.proxy.async.shared::cta;" ::: "memory");
        uint32_t saddr;
        asm("{ .reg .u64 tmp; cvta.to.shared.u64 tmp, %1; cvt.u32.u64 %0, tmp; }"
            : "=r"(saddr) : "l"(tile));
        const size_t gbase   = (size_t)blockIdx.x * TILE_FLOATS;
        const size_t bstride = (size_t)HW * 3;
#pragma unroll
        for (int n = 0; n < NBATCH; n++) {
            float* dst = out + gbase + (size_t)n * bstride;
            asm volatile(
                "cp.async.bulk.global.shared::cta.bulk_group [%0], [%1], %2;"
                :: "l"(dst), "r"(saddr), "n"(TILE_BYTES) : "memory");
        }
        asm volatile("cp.async.bulk.commit_group;" ::: "memory");
        asm volatile("cp.async.bulk.wait_group 0;" ::: "memory");
    }
}

extern "C" void kernel_launch(void* const* d_in, const int* in_sizes, int n_in,
                              void* d_out, int out_size)
{
    const float* verts = (const float*)d_in[0];
    const int*   faces = (const int*)d_in[1];
    const int*   pix   = (const int*)d_in[2];
    const float* bary  = (const float*)d_in[3];
    float* out = (float*)d_out;

    prep_kernel<<<(NUM_FACES + 255) / 256, 256>>>(verts, faces);
    uv_render_kernel<<<HW / PX_PER_TILE, THREADS>>>(pix, bary, out);
}

// round 12
// speedup vs baseline: 1.1635x; 1.0087x over previous
#include <cuda_runtime.h>
#include <cstdint>

// Problem constants
#define NUM_VERTS 6890
#define NUM_FACES 13776
#define HW (1024 * 1024)
#define NBATCH 16
#define THREADS 256
#define PX_PER_THREAD 2
#define PX_PER_TILE (THREADS * PX_PER_THREAD)   // 512
#define TILE_FLOATS (PX_PER_TILE * 3)           // 1536
#define TILE_BYTES (TILE_FLOATS * 4)            // 6144
#define NUM_BLOCKS (HW / PX_PER_TILE)           // 2048

// Exploits / lessons:
//  1. Reference uses only batch-0 faces/verts, broadcasts (H,W,3) over 16
//     batches -> compute once, TMA-replicate 16x from smem.
//  2. Index tensors are int32 on device (JAX x64 off).
//  3. L1-resident packed tables: float4 verts (110KB) + ushort4 faces (110KB)
//     = 220KB <= 228KB L1 (R11: best kernel time). Streams use __ldcs.
//  4. R12 fixes: (a) wait_group.READ instead of full wait -> block retires
//     while stores drain (was holding SM slot through 192KB commit);
//     (b) 2 px/thread -> regs ~40, occ 26%->~50%, better latency hiding
//     (R11: issue 3.3%, occ 26% = under-hidden gather latency).

__device__ __align__(16) float4  g_pvert[NUM_VERTS];   // (x,y,z,0) per vertex
__device__ __align__(8)  ushort4 g_pface[NUM_FACES];   // 3 vertex ids, packed

__global__ __launch_bounds__(256) void prep_kernel(
    const float* __restrict__ verts,   // (16, 6890, 3) — batch 0 only
    const int*   __restrict__ faces)   // (13776, 3) int32
{
    const int i = blockIdx.x * blockDim.x + threadIdx.x;
    if (i < NUM_FACES) {
        int v0 = faces[i * 3 + 0];
        int v1 = faces[i * 3 + 1];
        int v2 = faces[i * 3 + 2];
        v0 = (v0 < 0 || v0 >= NUM_VERTS) ? 0 : v0;
        v1 = (v1 < 0 || v1 >= NUM_VERTS) ? 0 : v1;
        v2 = (v2 < 0 || v2 >= NUM_VERTS) ? 0 : v2;
        g_pface[i] = make_ushort4((unsigned short)v0, (unsigned short)v1,
                                  (unsigned short)v2, 0);
    }
    if (i < NUM_VERTS) {
        const float* vp = verts + i * 3;
        g_pvert[i] = make_float4(vp[0], vp[1], vp[2], 0.0f);
    }
}

__global__ __launch_bounds__(THREADS) void uv_render_kernel(
    const int*   __restrict__ pix,     // (1024, 1024) int32
    const float* __restrict__ bary,    // (1024, 1024, 3) fp32
    float* __restrict__ out)           // (16, 1024, 1024, 3) fp32
{
    __shared__ __align__(128) float tile[TILE_FLOATS];   // 6 KB TMA source

    const int t  = blockIdx.x * blockDim.x + threadIdx.x;
    const int p0 = t * PX_PER_THREAD;

    // ---- streaming inputs, evict-first (preserve L1 for the two tables) ----
    const int2 pi = __ldcs(reinterpret_cast<const int2*>(pix + p0));
    int pf[2] = { pi.x, pi.y };

    const float2* b2 = reinterpret_cast<const float2*>(bary + (size_t)p0 * 3);
    float2 bA = __ldcs(b2 + 0), bB = __ldcs(b2 + 1), bC = __ldcs(b2 + 2);
    const float bar[6] = { bA.x, bA.y, bB.x, bB.y, bC.x, bC.y };

    // ---- 2 face records: independent LDG.64 into 110KB L1-hot table ----
    ushort4 q[2];
#pragma unroll
    for (int i = 0; i < 2; i++) {
        int f = pf[i];
        f = (f < 0 || f >= NUM_FACES) ? 0 : f;   // bg -> face 0, masked later
        q[i] = g_pface[f];
    }

    // ---- 6 vertex records: independent LDG.128 into 110KB L1-hot table ----
    float res[6];
#pragma unroll
    for (int i = 0; i < 2; i++) {
        float4 v0 = g_pvert[q[i].x];
        float4 v1 = g_pvert[q[i].y];
        float4 v2 = g_pvert[q[i].z];
        const float m  = (pf[i] >= 0) ? 1.0f : 0.0f;
        const float b0 = bar[i * 3 + 0], b1 = bar[i * 3 + 1], b2c = bar[i * 3 + 2];
        res[i * 3 + 0] = (b0 * v0.x + b1 * v1.x + b2c * v2.x) * m;
        res[i * 3 + 1] = (b0 * v0.y + b1 * v1.y + b2c * v2.y) * m;
        res[i * 3 + 2] = (b0 * v0.z + b1 * v1.z + b2c * v2.z) * m;
    }

    // ---- result tile to smem (3x STS.64, 8B-aligned) ----
    {
        float2* t2 = reinterpret_cast<float2*>(tile) + threadIdx.x * 3;
        t2[0] = make_float2(res[0], res[1]);
        t2[1] = make_float2(res[2], res[3]);
        t2[2] = make_float2(res[4], res[5]);
    }
    __syncthreads();

    // ---- thread0: TMA bulk-store tile to all 16 batch slices ----
    if (threadIdx.x == 0) {
        asm volatile("fence.proxy.async.shared::cta;" ::: "memory");
        uint32_t saddr;
        asm("{ .reg .u64 tmp; cvta.to.shared.u64 tmp, %1; cvt.u32.u64 %0, tmp; }"
            : "=r"(saddr) : "l"(tile));
        const size_t gbase   = (size_t)blockIdx.x * TILE_FLOATS;
        const size_t bstride = (size_t)HW * 3;
#pragma unroll
        for (int n = 0; n < NBATCH; n++) {
            float* dst = out + gbase + (size_t)n * bstride;
            asm volatile(
                "cp.async.bulk.global.shared::cta.bulk_group [%0], [%1], %2;"
                :: "l"(dst), "r"(saddr), "n"(TILE_BYTES) : "memory");
        }
        asm volatile("cp.async.bulk.commit_group;" ::: "memory");
        // Wait only until the TMA engine has READ smem; the block may retire
        // while the global writes drain (overlaps with the next wave).
        asm volatile("cp.async.bulk.wait_group.read 0;" ::: "memory");
    }
}

extern "C" void kernel_launch(void* const* d_in, const int* in_sizes, int n_in,
                              void* d_out, int out_size)
{
    const float* verts = (const float*)d_in[0];
    const int*   faces = (const int*)d_in[1];
    const int*   pix   = (const int*)d_in[2];
    const float* bary  = (const float*)d_in[3];
    float* out = (float*)d_out;

    prep_kernel<<<(NUM_FACES + 255) / 256, 256>>>(verts, faces);
    uv_render_kernel<<<NUM_BLOCKS, THREADS>>>(pix, bary, out);
}